// round 9
// baseline (speedup 1.0000x reference)
#include <cuda_runtime.h>
#include <cuda_fp16.h>
#include <cstdint>

#define C_DIM   256
#define HGT     192
#define WID     192
#define HW      (HGT*WID)
#define CHW     (C_DIM*HW)
#define BATCH   2
#define NWIN    12
#define WINS_B  (NWIN*NWIN)
#define NWINS   (BATCH*WINS_B)      // 288
#define HEADS   8
#define HD      32
#define S_TOK   256
#define NWH     (NWINS*HEADS)       // 2304
#define SCALE_F 0.17677669529663688f

// ---------------- scratch (fp16 intermediates) -------------------------------
__device__ __half g_qh[(size_t)NWH * S_TOK * HD];         // [wh][s][d]
__device__ __half g_kh[(size_t)NWH * S_TOK * HD];         // [wh][t][d]
__device__ __half g_vh[(size_t)NWH * HD * S_TOK];         // [wh][d][t]
__device__ __half g_attnh[(size_t)NWINS * S_TOK * C_DIM]; // [win][s][c]
__device__ __half g_wh[4 * C_DIM * C_DIM];                // Wq,Wk,Wv,Wo fp16
__device__ __half g_xth[(size_t)2 * BATCH * WINS_B * S_TOK * C_DIM]; // [img][b][win][s][c]

// ---------------- helpers ----------------------------------------------------
__device__ __forceinline__ void mma_f16(float c[4],
                                        const uint32_t a[4],
                                        const uint32_t b[2]) {
    asm volatile(
        "mma.sync.aligned.m16n8k16.row.col.f32.f16.f16.f32 "
        "{%0,%1,%2,%3},{%4,%5,%6,%7},{%8,%9},{%0,%1,%2,%3};"
        : "+f"(c[0]), "+f"(c[1]), "+f"(c[2]), "+f"(c[3])
        : "r"(a[0]), "r"(a[1]), "r"(a[2]), "r"(a[3]),
          "r"(b[0]), "r"(b[1]));
}

__device__ __forceinline__ void cp_async16(void* smem, const void* gmem) {
    unsigned sa = (unsigned)__cvta_generic_to_shared(smem);
    asm volatile("cp.async.cg.shared.global [%0], [%1], 16;" :: "r"(sa), "l"(gmem));
}
__device__ __forceinline__ void cp_commit() {
    asm volatile("cp.async.commit_group;");
}
template<int N> __device__ __forceinline__ void cp_wait() {
    asm volatile("cp.async.wait_group %0;" :: "n"(N));
}
__device__ __forceinline__ uint32_t ldu32(const __half* p) {
    return *reinterpret_cast<const uint32_t*>(p);
}

// ---------------- weight conversion ------------------------------------------
__global__ void conv_w_kernel(const float* __restrict__ Wq,
                              const float* __restrict__ Wk,
                              const float* __restrict__ Wv,
                              const float* __restrict__ Wo)
{
    int i = blockIdx.x * blockDim.x + threadIdx.x;
    if (i < C_DIM * C_DIM) {
        g_wh[                 i] = __float2half_rn(Wq[i]);
        g_wh[  C_DIM*C_DIM + i] = __float2half_rn(Wk[i]);
        g_wh[2*C_DIM*C_DIM + i] = __float2half_rn(Wv[i]);
        g_wh[3*C_DIM*C_DIM + i] = __float2half_rn(Wo[i]);
    }
}

// ---------------- x convert + windowize: [c][h][w] fp32 -> [win][s][c] fp16 ---
__global__ __launch_bounds__(256)
void conv_x_kernel(const float* __restrict__ x_q,
                   const float* __restrict__ x_kv)
{
    __shared__ float ts[32][257];

    const int wi  = blockIdx.x;
    const int b   = blockIdx.y;
    const int img = blockIdx.z;
    const int tid = threadIdx.x;

    const float* src = (img ? x_kv : x_q) + (size_t)b * CHW;
    __half* dst = g_xth + ((size_t)img * BATCH * WINS_B
                         + (size_t)b * WINS_B + wi) * (S_TOK * C_DIM);

    const int h0 = (wi / NWIN) * 16;
    const int w0 = (wi % NWIN) * 16;
    const int pix = (h0 + (tid >> 4)) * WID + w0 + (tid & 15);

    for (int cc = 0; cc < 8; ++cc) {
        #pragma unroll
        for (int i = 0; i < 32; ++i)
            ts[i][tid] = src[(size_t)(cc * 32 + i) * HW + pix];
        __syncthreads();
        #pragma unroll
        for (int j = 0; j < 16; ++j) {
            int linear = j * 256 + tid;
            int s  = linear >> 4;
            int cp = linear & 15;
            *reinterpret_cast<__half2*>(dst + (size_t)s * C_DIM + cc * 32 + cp * 2)
                = __floats2half2_rn(ts[cp * 2][s], ts[cp * 2 + 1][s]);
        }
        __syncthreads();
    }
}

// ---------------- projection GEMM (fp16 mma, all modes direct-B) -------------
// out[m,n] = sum_k W[m,k] * X[k,n] + bias[m]
// B (X^T) is fp16 [token][c] in window-token order for every mode.
#define G_LD   40
#define G_AB_H (128 * G_LD)                    // 5120 halves per tile
#define GEMM_SMEM (3 * G_AB_H * 2 * 2)         // 61,440 B

template<int MODE>
__global__ __launch_bounds__(128, 2)
void gemm_f16_kernel(const __half* __restrict__ Wh,
                     const __half* __restrict__ Xh,
                     const float* __restrict__ bias,
                     float* __restrict__ out_img)
{
    extern __shared__ char smraw[];
    __half* Ah = (__half*)smraw;               // [3][5120]
    __half* Bh = Ah + 3 * G_AB_H;              // [3][5120]

    const int n0  = blockIdx.x * 128;
    const int m0  = blockIdx.y * 128;
    const int b   = blockIdx.z;
    const int tid  = threadIdx.x;
    const int lane = tid & 31;
    const int warp = tid >> 5;
    const int wm   = warp & 1;
    const int wn   = warp >> 1;
    const int g    = lane >> 2;
    const int tig  = lane & 3;

    const __half* Xbh = Xh + ((size_t)(b * WINS_B + (n0 >> 8)) * S_TOK
                              + (n0 & 255)) * (size_t)C_DIM;

    float acc[4][8][4];
    #pragma unroll
    for (int i = 0; i < 4; ++i)
        #pragma unroll
        for (int j = 0; j < 8; ++j)
            #pragma unroll
            for (int r = 0; r < 4; ++r) acc[i][j][r] = 0.f;

    auto load_stage = [&](int kb, int st) {
        const int k0 = kb * 32;
        __half* As = Ah + st * G_AB_H;
        __half* Bs = Bh + st * G_AB_H;
        #pragma unroll
        for (int i = 0; i < 4; ++i) {
            int idx = i * 128 + tid;
            int row = idx >> 2, c8 = (idx & 3) << 3;
            cp_async16(As + row * G_LD + c8,
                       Wh + (size_t)(m0 + row) * C_DIM + k0 + c8);
            cp_async16(Bs + row * G_LD + c8,
                       Xbh + (size_t)row * C_DIM + k0 + c8);
        }
        cp_commit();
    };

    load_stage(0, 0);
    load_stage(1, 1);

    for (int kb = 0; kb < 8; ++kb) {
        const int st = kb % 3;
        if (kb < 7) cp_wait<1>(); else cp_wait<0>();
        __syncthreads();
        if (kb + 2 < 8) load_stage(kb + 2, (kb + 2) % 3);

        const __half* Ab = Ah + st * G_AB_H;
        const __half* Bb = Bh + st * G_AB_H;
        #pragma unroll
        for (int ks = 0; ks < 2; ++ks) {
            uint32_t af[4][4];
            #pragma unroll
            for (int fm = 0; fm < 4; ++fm) {
                int rb = wm * 64 + fm * 16;
                const __half* base = Ab + ks * 16 + 2 * tig;
                af[fm][0] = ldu32(base + (rb + g    ) * G_LD);
                af[fm][1] = ldu32(base + (rb + g + 8) * G_LD);
                af[fm][2] = ldu32(base + (rb + g    ) * G_LD + 8);
                af[fm][3] = ldu32(base + (rb + g + 8) * G_LD + 8);
            }
            uint32_t bf[8][2];
            #pragma unroll
            for (int fn = 0; fn < 8; ++fn) {
                int nb = wn * 64 + fn * 8;
                const __half* base = Bb + ks * 16 + 2 * tig;
                bf[fn][0] = ldu32(base + (nb + g) * G_LD);
                bf[fn][1] = ldu32(base + (nb + g) * G_LD + 8);
            }
            #pragma unroll
            for (int fm = 0; fm < 4; ++fm)
                #pragma unroll
                for (int fn = 0; fn < 8; ++fn)
                    mma_f16(acc[fm][fn], af[fm], bf[fn]);
        }
    }

    // -------- epilogue (n is window-token order for all modes) --------
    if (MODE < 3) {
        const float sc = (MODE == 0) ? SCALE_F : 1.0f;
        #pragma unroll
        for (int fm = 0; fm < 4; ++fm) {
            int row0 = m0 + wm * 64 + fm * 16 + g;
            int row1 = row0 + 8;
            float b0v = bias[row0], b1v = bias[row1];
            int head0 = row0 >> 5, hd0 = row0 & 31;
            int head1 = row1 >> 5, hd1 = row1 & 31;
            #pragma unroll
            for (int fn = 0; fn < 8; ++fn) {
                int ncol = n0 + wn * 64 + fn * 8 + tig * 2;
                #pragma unroll
                for (int e = 0; e < 2; ++e) {
                    int n   = ncol + e;
                    int win = b * WINS_B + (n >> 8);
                    int s   = n & 255;
                    __half v0 = __float2half_rn((acc[fm][fn][e]     + b0v) * sc);
                    __half v1 = __float2half_rn((acc[fm][fn][2 + e] + b1v) * sc);
                    if (MODE == 2) {
                        g_vh[((size_t)(win * HEADS + head0) * HD + hd0) * S_TOK + s] = v0;
                        g_vh[((size_t)(win * HEADS + head1) * HD + hd1) * S_TOK + s] = v1;
                    } else {
                        __half* dst = (MODE == 0) ? g_qh : g_kh;
                        dst[((size_t)(win * HEADS + head0) * S_TOK + s) * HD + hd0] = v0;
                        dst[((size_t)(win * HEADS + head1) * S_TOK + s) * HD + hd1] = v1;
                    }
                }
            }
        }
    } else {
        #pragma unroll
        for (int fm = 0; fm < 4; ++fm) {
            int row0 = m0 + wm * 64 + fm * 16 + g;
            int row1 = row0 + 8;
            float b0v = bias[row0], b1v = bias[row1];
            float* o0 = out_img + (size_t)b * CHW + (size_t)row0 * HW;
            float* o1 = out_img + (size_t)b * CHW + (size_t)row1 * HW;
            #pragma unroll
            for (int fn = 0; fn < 8; ++fn) {
                int ncol = n0 + wn * 64 + fn * 8 + tig * 2;
                #pragma unroll
                for (int e = 0; e < 2; ++e) {
                    int n  = ncol + e;
                    int wl = n >> 8;
                    int s  = n & 255;
                    int h  = ((wl / NWIN) << 4) | (s >> 4);
                    int w  = ((wl % NWIN) << 4) | (s & 15);
                    int pix = h * WID + w;
                    o0[pix] = acc[fm][fn][e]     + b0v;
                    o1[pix] = acc[fm][fn][2 + e] + b1v;
                }
            }
        }
    }
}

// ---------------- attention core (fp16 mma, flash-style; unchanged R8) -------
#define AT_LD   40
#define AT_VLD  264
#define ATT_SMEM ((S_TOK*AT_LD + HD*AT_VLD + S_TOK*AT_LD) * 2)   // 57,856 B

__global__ __launch_bounds__(256, 2)
void attn_f16_kernel()
{
    extern __shared__ char smraw[];
    __half* Ksh = (__half*)smraw;                 // [256][40]
    __half* Vsh = Ksh + S_TOK * AT_LD;            // [32][264]
    __half* QP  = Vsh + HD * AT_VLD;              // Q staging, then P

    const int wh   = blockIdx.x;
    const int tid  = threadIdx.x;
    const int lane = tid & 31;
    const int warp = tid >> 5;
    const int g    = lane >> 2;
    const int tig  = lane & 3;

    const __half* qb = g_qh + (size_t)wh * (S_TOK * HD);
    const __half* kb = g_kh + (size_t)wh * (S_TOK * HD);
    const __half* vb = g_vh + (size_t)wh * (HD * S_TOK);

    #pragma unroll
    for (int i = 0; i < 4; ++i) {
        int idx = i * 256 + tid;
        int r   = idx >> 2, c8 = (idx & 3) << 3;
        cp_async16(Ksh + r * AT_LD + c8, kb + r * HD + c8);
        cp_async16(QP  + r * AT_LD + c8, qb + r * HD + c8);
        int d = idx >> 5, cv = (idx & 31) << 3;
        cp_async16(Vsh + d * AT_VLD + cv, vb + d * S_TOK + cv);
    }
    cp_commit();
    cp_wait<0>();
    __syncthreads();

    const int mb = warp * 32;
    uint32_t Qf[2][2][4];
    #pragma unroll
    for (int mt = 0; mt < 2; ++mt)
        #pragma unroll
        for (int ks = 0; ks < 2; ++ks) {
            int rb = mb + mt * 16;
            const __half* base = QP + ks * 16 + 2 * tig;
            Qf[mt][ks][0] = ldu32(base + (rb + g    ) * AT_LD);
            Qf[mt][ks][1] = ldu32(base + (rb + g + 8) * AT_LD);
            Qf[mt][ks][2] = ldu32(base + (rb + g    ) * AT_LD + 8);
            Qf[mt][ks][3] = ldu32(base + (rb + g + 8) * AT_LD + 8);
        }
    __syncthreads();

    __half* Pw = QP + warp * (32 * AT_LD);

    float Oa[2][4][4];
    #pragma unroll
    for (int mt = 0; mt < 2; ++mt)
        #pragma unroll
        for (int nd = 0; nd < 4; ++nd)
            #pragma unroll
            for (int r = 0; r < 4; ++r) Oa[mt][nd][r] = 0.f;
    float rs[4] = {0.f, 0.f, 0.f, 0.f};

    for (int kt = 0; kt < 8; ++kt) {
        const int t0 = kt * 32;
        float Sa[2][4][4];
        #pragma unroll
        for (int mt = 0; mt < 2; ++mt)
            #pragma unroll
            for (int n = 0; n < 4; ++n)
                #pragma unroll
                for (int r = 0; r < 4; ++r) Sa[mt][n][r] = 0.f;

        #pragma unroll
        for (int ks = 0; ks < 2; ++ks)
            #pragma unroll
            for (int nt = 0; nt < 4; ++nt) {
                const __half* base = Ksh + (t0 + nt * 8 + g) * AT_LD
                                         + ks * 16 + 2 * tig;
                uint32_t bfr[2];
                bfr[0] = ldu32(base);
                bfr[1] = ldu32(base + 8);
                mma_f16(Sa[0][nt], Qf[0][ks], bfr);
                mma_f16(Sa[1][nt], Qf[1][ks], bfr);
            }

        #pragma unroll
        for (int mt = 0; mt < 2; ++mt)
            #pragma unroll
            for (int nt = 0; nt < 4; ++nt) {
                float p0 = __expf(Sa[mt][nt][0]);
                float p1 = __expf(Sa[mt][nt][1]);
                float p2 = __expf(Sa[mt][nt][2]);
                float p3 = __expf(Sa[mt][nt][3]);
                rs[mt*2 + 0] += p0 + p1;
                rs[mt*2 + 1] += p2 + p3;
                *reinterpret_cast<__half2*>(
                    Pw + (mt*16 + g    ) * AT_LD + nt*8 + 2*tig)
                    = __floats2half2_rn(p0, p1);
                *reinterpret_cast<__half2*>(
                    Pw + (mt*16 + g + 8) * AT_LD + nt*8 + 2*tig)
                    = __floats2half2_rn(p2, p3);
            }
        __syncwarp();

        #pragma unroll
        for (int ks = 0; ks < 2; ++ks) {
            uint32_t a[2][4];
            #pragma unroll
            for (int mt = 0; mt < 2; ++mt) {
                const __half* base = Pw + ks * 16 + 2 * tig;
                a[mt][0] = ldu32(base + (mt*16 + g    ) * AT_LD);
                a[mt][1] = ldu32(base + (mt*16 + g + 8) * AT_LD);
                a[mt][2] = ldu32(base + (mt*16 + g    ) * AT_LD + 8);
                a[mt][3] = ldu32(base + (mt*16 + g + 8) * AT_LD + 8);
            }
            #pragma unroll
            for (int nd = 0; nd < 4; ++nd) {
                const __half* base = Vsh + (nd*8 + g) * AT_VLD
                                         + t0 + ks * 16 + 2 * tig;
                uint32_t bfr[2];
                bfr[0] = ldu32(base);
                bfr[1] = ldu32(base + 8);
                mma_f16(Oa[0][nd], a[0], bfr);
                mma_f16(Oa[1][nd], a[1], bfr);
            }
        }
        __syncwarp();
    }

    #pragma unroll
    for (int r = 0; r < 4; ++r) {
        rs[r] += __shfl_xor_sync(0xffffffffu, rs[r], 1);
        rs[r] += __shfl_xor_sync(0xffffffffu, rs[r], 2);
    }
    float inv[4];
    #pragma unroll
    for (int r = 0; r < 4; ++r) inv[r] = 1.0f / rs[r];

    const int win  = wh >> 3;
    const int head = wh & 7;
    __half* ob = g_attnh + (size_t)win * (S_TOK * C_DIM) + head * HD;
    #pragma unroll
    for (int mt = 0; mt < 2; ++mt)
        #pragma unroll
        for (int nd = 0; nd < 4; ++nd) {
            int s0 = mb + mt * 16 + g;
            int d0 = nd * 8 + 2 * tig;
            *reinterpret_cast<__half2*>(ob + (size_t)s0 * C_DIM + d0)
                = __floats2half2_rn(Oa[mt][nd][0] * inv[mt*2],
                                    Oa[mt][nd][1] * inv[mt*2]);
            *reinterpret_cast<__half2*>(ob + (size_t)(s0 + 8) * C_DIM + d0)
                = __floats2half2_rn(Oa[mt][nd][2] * inv[mt*2 + 1],
                                    Oa[mt][nd][3] * inv[mt*2 + 1]);
        }
}

// ---------------- launch ---------------------------------------------------
extern "C" void kernel_launch(void* const* d_in, const int* in_sizes, int n_in,
                              void* d_out, int out_size)
{
    const float* x_q  = (const float*)d_in[0];
    const float* x_kv = (const float*)d_in[1];
    const float* Wq   = (const float*)d_in[2];
    const float* bq   = (const float*)d_in[3];
    const float* Wk   = (const float*)d_in[4];
    const float* bk   = (const float*)d_in[5];
    const float* Wv   = (const float*)d_in[6];
    const float* bv   = (const float*)d_in[7];
    const float* Wo   = (const float*)d_in[8];
    const float* bo   = (const float*)d_in[9];
    float* out = (float*)d_out;

    cudaFuncSetAttribute(gemm_f16_kernel<0>,
                         cudaFuncAttributeMaxDynamicSharedMemorySize, GEMM_SMEM);
    cudaFuncSetAttribute(gemm_f16_kernel<1>,
                         cudaFuncAttributeMaxDynamicSharedMemorySize, GEMM_SMEM);
    cudaFuncSetAttribute(gemm_f16_kernel<2>,
                         cudaFuncAttributeMaxDynamicSharedMemorySize, GEMM_SMEM);
    cudaFuncSetAttribute(gemm_f16_kernel<3>,
                         cudaFuncAttributeMaxDynamicSharedMemorySize, GEMM_SMEM);
    cudaFuncSetAttribute(attn_f16_kernel,
                         cudaFuncAttributeMaxDynamicSharedMemorySize, ATT_SMEM);

    __half *wh_base, *xt_base, *attn_base;
    cudaGetSymbolAddress((void**)&wh_base,   g_wh);
    cudaGetSymbolAddress((void**)&xt_base,   g_xth);
    cudaGetSymbolAddress((void**)&attn_base, g_attnh);
    const size_t img_str = (size_t)BATCH * WINS_B * S_TOK * C_DIM;

    conv_w_kernel<<<256, 256>>>(Wq, Wk, Wv, Wo);
    conv_x_kernel<<<dim3(WINS_B, BATCH, 2), 256>>>(x_q, x_kv);

    dim3 ggrid(HW / 128, 2, BATCH);   // (288, 2, 2)
    gemm_f16_kernel<0><<<ggrid, 128, GEMM_SMEM>>>(wh_base,                 xt_base,           bq, nullptr);
    gemm_f16_kernel<1><<<ggrid, 128, GEMM_SMEM>>>(wh_base +   C_DIM*C_DIM, xt_base + img_str, bk, nullptr);
    gemm_f16_kernel<2><<<ggrid, 128, GEMM_SMEM>>>(wh_base + 2*C_DIM*C_DIM, xt_base + img_str, bv, nullptr);
    attn_f16_kernel<<<NWH, 256, ATT_SMEM>>>();
    gemm_f16_kernel<3><<<ggrid, 128, GEMM_SMEM>>>(wh_base + 3*C_DIM*C_DIM, attn_base,         bo, out);
}